// round 11
// baseline (speedup 1.0000x reference)
#include <cuda_runtime.h>
#include <cmath>

#define PITCH 68
#define NB (64 * PITCH)   // 4352 floats per padded 64x64 std buffer
#define VPU 68            // vertical pitch in ull units (32 pair-rows x 68)

typedef unsigned long long ull;

// Host-built tap tables passed by value (~22 KB kernel param space).
// d [m*8+rg]  = {g(s),g(s),g(s+1),g(s+1)},  s = 8*rg + 2*m - 64  (dup-quads, left)
// p [m*16+c]  = {g(s),g(s+1),g(s+1),g(s+2)}, s = 4*c + 2*m - 64  (pair-quads, right std)
// td[m*16+c]  = {g(s),g(s),g(s+1),g(s+1)},   s = 4*c + 2*m - 64  (dup-quads, right vert)
struct TapParam { float4 d[288]; float4 p[544]; float4 td[544]; };

__device__ __forceinline__ ull f2x2(float lo, float hi) {
    ull r; asm("mov.b64 %0, {%1, %2};" : "=l"(r) : "f"(lo), "f"(hi)); return r;
}
__device__ __forceinline__ float2 unpk(ull v) {
    float2 r; asm("mov.b64 {%0, %1}, %2;" : "=f"(r.x), "=f"(r.y) : "l"(v)); return r;
}
__device__ __forceinline__ void ffma2(ull& d, ull a, ull b) {
    asm("fma.rn.f32x2 %0, %1, %2, %0;" : "+l"(d) : "l"(a), "l"(b));
}
__device__ __forceinline__ ull addp(ull a, ull b) {
    ull r; asm("add.rn.f32x2 %0, %1, %2;" : "=l"(r) : "l"(a), "l"(b)); return r;
}
__device__ __forceinline__ ull mulp(ull a, ull b) {
    ull r; asm("mul.rn.f32x2 %0, %1, %2;" : "=l"(r) : "l"(a), "l"(b)); return r;
}

// Left dup taps: t[w] = dup g(8rg - kb - 7 - SH + w), w in [0,15). (R10, proven)
template<int SH>
__device__ __forceinline__ void load_ldtaps(ull t[15], const ulonglong2* __restrict__ D,
                                            int kb, int rg) {
    const ulonglong2* dp = D + (28 - (kb >> 1)) * 8 + rg;
    ulonglong2 e[8];
    #pragma unroll
    for (int j = 0; j < 8; j++) e[j] = dp[j * 8];
    #pragma unroll
    for (int w = 0; w < 15; w++) {
        if (SH == 0) t[w] = (w & 1) ? e[(w + 1) >> 1].x : e[w >> 1].y;
        else         t[w] = (w & 1) ? e[w >> 1].y       : e[w >> 1].x;
    }
}

// Right pair taps (R10, proven): t[w] = pair(g(4cg - kb - SH - 7 + w), ...).
template<int SH>
__device__ __forceinline__ void load_rtaps(ull t[10], const ulonglong2* __restrict__ TU,
                                           int kb, int cg) {
    const ulonglong2* tp = TU + (28 - (kb >> 1)) * 16 + cg;
    ulonglong2 e[6];
    #pragma unroll
    for (int j = 0; j < (SH ? 5 : 6); j++) e[j] = tp[j * 16];
    #pragma unroll
    for (int w = 0; w < 10; w++) {
        if (SH) t[w] = (w & 1) ? e[w >> 1].y : e[w >> 1].x;
        else    t[w] = (w & 1) ? e[(w + 1) >> 1].x : e[w >> 1].y;
    }
}

// Right dup taps for vertical form: t[w] = dup g(4cg - kb - SH - 7 + w), w in [0,11).
template<int SH>
__device__ __forceinline__ void load_vtaps(ull t[11], const ulonglong2* __restrict__ TD,
                                           int kb, int cg) {
    const ulonglong2* tp = TD + (28 - (kb >> 1)) * 16 + cg;
    ulonglong2 e[6];
    #pragma unroll
    for (int j = 0; j < 6; j++) e[j] = tp[j * 16];
    #pragma unroll
    for (int w = 0; w <= 10; w++) {
        const int u = w + 1 - SH;
        t[w] = (u & 1) ? e[u >> 1].y : e[u >> 1].x;
    }
}

// Left circulant, 8x4 tile, col-pair acc, MOV-free (R10, proven).
template<int SH>
__device__ __forceinline__ void mm_left8(ull acc[8][2], const float* __restrict__ src,
                                         const ulonglong2* __restrict__ D,
                                         int rg, int c0) {
    #pragma unroll
    for (int r = 0; r < 8; r++) { acc[r][0] = 0ull; acc[r][1] = 0ull; }
    #pragma unroll 1
    for (int kb = 0; kb < 64; kb += 8) {
        ull t[15];
        load_ldtaps<SH>(t, D, kb, rg);
        #pragma unroll
        for (int q = 0; q < 8; q++) {
            ulonglong2 s = *(const ulonglong2*)&src[(kb + q) * PITCH + c0];
            #pragma unroll
            for (int r = 0; r < 8; r++) {
                ull a = t[r - q + 7];
                ffma2(acc[r][0], a, s.x);
                ffma2(acc[r][1], a, s.y);
            }
        }
    }
}

// Right circulant^T, std src, col-pair acc (R10, proven; used for P1 a2 only).
template<int SH>
__device__ __forceinline__ void mm_right8(ull acc[8][2], const float* __restrict__ src,
                                          const ulonglong2* __restrict__ TU,
                                          int r0, int cg) {
    #pragma unroll
    for (int r = 0; r < 8; r++) { acc[r][0] = 0ull; acc[r][1] = 0ull; }
    #pragma unroll 1
    for (int kb = 0; kb < 64; kb += 8) {
        ull t[10];
        load_rtaps<SH>(t, TU, kb, cg);
        #pragma unroll
        for (int i = 0; i < 8; i++) {
            float4 va = *(const float4*)&src[(r0 + i) * PITCH + kb];
            float4 vb = *(const float4*)&src[(r0 + i) * PITCH + kb + 4];
            float sv[8] = {va.x, va.y, va.z, va.w, vb.x, vb.y, vb.z, vb.w};
            #pragma unroll
            for (int q = 0; q < 8; q++) {
                ull sd = f2x2(sv[q], sv[q]);
                ffma2(acc[i][0], sd, t[7 - q]);
                ffma2(acc[i][1], sd, t[9 - q]);
            }
        }
    }
}

// Right circulant^T, VERTICAL src, row-pair acc, MOV-free:
// SV[ph*VPU+k] = {v[2ph][k], v[2ph+1][k]};
// acc[j][c] = {dst[2(ph0+j)][c0+c], dst[2(ph0+j)+1][c0+c]},
// dst[i][m] = sum_k v[i][k] g(m-k-SH).
template<int SH>
__device__ __forceinline__ void mm_rightV(ull acc[4][4], const ull* __restrict__ SV,
                                          const ulonglong2* __restrict__ TD,
                                          int ph0, int cg) {
    #pragma unroll
    for (int j = 0; j < 4; j++)
        #pragma unroll
        for (int c = 0; c < 4; c++) acc[j][c] = 0ull;
    #pragma unroll 1
    for (int kb = 0; kb < 64; kb += 8) {
        ull t[11];
        load_vtaps<SH>(t, TD, kb, cg);
        #pragma unroll
        for (int j = 0; j < 4; j++) {
            const ull* row = SV + (ph0 + j) * VPU + kb;
            ulonglong2 s0 = *(const ulonglong2*)&row[0];
            ulonglong2 s1 = *(const ulonglong2*)&row[2];
            ulonglong2 s2 = *(const ulonglong2*)&row[4];
            ulonglong2 s3 = *(const ulonglong2*)&row[6];
            ull sk[8] = {s0.x, s0.y, s1.x, s1.y, s2.x, s2.y, s3.x, s3.y};
            #pragma unroll
            for (int q = 0; q < 8; q++)
                #pragma unroll
                for (int c = 0; c < 4; c++)
                    ffma2(acc[j][c], sk[q], t[c - q + 7]);
        }
    }
}

__device__ __forceinline__ void store8(float* __restrict__ dst, ull acc[8][2],
                                       int r0, int c0) {
    #pragma unroll
    for (int r = 0; r < 8; r++) {
        ulonglong2 o; o.x = acc[r][0]; o.y = acc[r][1];
        *(ulonglong2*)&dst[(r0 + r) * PITCH + c0] = o;
    }
}

// Butterfly-reduce 8 lane-local floats over cg (masks 8..1 within 16-lane halves).
__device__ __forceinline__ void bfly16(float v[8]) {
    #pragma unroll
    for (int o = 8; o >= 1; o >>= 1)
        #pragma unroll
        for (int r = 0; r < 8; r++)
            v[r] += __shfl_xor_sync(~0u, v[r], o);
}

__global__ void __launch_bounds__(128, 3)
uppolyact_kernel(const float* __restrict__ xg,
                 const float* __restrict__ coef,
                 float* __restrict__ outg,
                 const TapParam tab) {
    extern __shared__ float sm[];
    float* B0 = sm;            // x (std)      -> oo^2 (vert)
    float* B1 = sm + NB;       // Gx (vert)    -> eo^2 (vert)
    float* B2 = sm + 2 * NB;   // xG^T (std)   -> oe^2 (std) -> tmp (std)
    ull* V0 = (ull*)B0; ull* V1 = (ull*)B1;
    ulonglong2* Dup = (ulonglong2*)(sm + 3 * NB);  // 288
    ulonglong2* TU  = Dup + 288;                   // 544
    ulonglong2* TD  = TU + 544;                    // 544
    float* Pr  = (float*)(TD + 544);   // 4 x 68 cross-warp partials
    float* rs  = Pr + 272;             // 64
    float* cs  = rs + 64;              // 64
    float* rs1 = cs + 64;              // 64
    float* cs2 = rs1 + 64;             // 64
    float* tsp = cs2 + 64;             // 1

    const int tid = threadIdx.x;
    const int rg = tid >> 4, cg = tid & 15;
    const int r0 = rg << 3, c0 = cg << 2;
    const int ph0 = rg << 2;           // 4 pair-rows per thread
    const int lane = tid & 31, wrp = tid >> 5;
    const float* xin = xg + (size_t)blockIdx.x * 4096;
    float* outp = outg + (size_t)blockIdx.x * 4096;
    const float inv64 = 1.0f / 64.0f;

    const float k0 = __ldg(&coef[0]), k1 = __ldg(&coef[1]);
    const float k2q = 0.25f * __ldg(&coef[2]);

    // ---- P0: tables -> smem; load image std; rs partials (smem) + cs (shuffle) ----
    {
        const float4* s4 = (const float4*)&tab;
        float4* d4 = (float4*)Dup;                // Dup|TU|TD contiguous, 1376 float4
        #pragma unroll
        for (int i = tid; i < 1376; i += 128) d4[i] = s4[i];
    }
    {
        float4 xv[8];
        #pragma unroll
        for (int r = 0; r < 8; r++) {
            xv[r] = *(const float4*)&xin[(r0 + r) * 64 + c0];
            *(float4*)&B0[(r0 + r) * PITCH + c0] = xv[r];
        }
        float4 pr = make_float4(0.f, 0.f, 0.f, 0.f);    // alt-sum over 8 rows
        #pragma unroll
        for (int r = 0; r < 8; r++) {
            float sg = (r & 1) ? -1.f : 1.f;
            pr.x += sg * xv[r].x; pr.y += sg * xv[r].y;
            pr.z += sg * xv[r].z; pr.w += sg * xv[r].w;
        }
        pr.x += __shfl_xor_sync(~0u, pr.x, 16);
        pr.y += __shfl_xor_sync(~0u, pr.y, 16);
        pr.z += __shfl_xor_sync(~0u, pr.z, 16);
        pr.w += __shfl_xor_sync(~0u, pr.w, 16);
        if (lane < 16) *(float4*)&Pr[wrp * 68 + c0] = pr;
        float pc[8];                                     // alt-sum over 4 cols
        #pragma unroll
        for (int r = 0; r < 8; r++)
            pc[r] = xv[r].x - xv[r].y + xv[r].z - xv[r].w;
        bfly16(pc);
        if (cg == 0) {
            *(float4*)&cs[r0]     = make_float4(pc[0], pc[1], pc[2], pc[3]);
            *(float4*)&cs[r0 + 4] = make_float4(pc[4], pc[5], pc[6], pc[7]);
        }
    }
    __syncthreads();

    // ---- P1: rs reduce + a1 = Gx (left -> B1 vertical) ; a2 = xG^T (std -> B2) ----
    if (tid < 64) {
        float s = 0.f;
        #pragma unroll
        for (int w = 0; w < 4; w++) s += Pr[w * 68 + tid];
        rs[tid] = s;
    }
    {
        ull a1[8][2];
        mm_left8<0>(a1, B0, Dup, rg, c0);
        // cs2 partials (alt col-sums of Gx) via shuffle
        float pc[8];
        #pragma unroll
        for (int r = 0; r < 8; r++) {
            float2 u = unpk(a1[r][0]), w = unpk(a1[r][1]);
            pc[r] = u.x - u.y + w.x - w.y;
        }
        bfly16(pc);
        if (cg == 0) {
            *(float4*)&cs2[r0]     = make_float4(pc[0], pc[1], pc[2], pc[3]);
            *(float4*)&cs2[r0 + 4] = make_float4(pc[4], pc[5], pc[6], pc[7]);
        }
        // store Gx VERTICAL into B1: pair {row 2ph, 2ph+1} per col
        #pragma unroll
        for (int j = 0; j < 4; j++) {
            float2 a0 = unpk(a1[2 * j][0]),     a1v = unpk(a1[2 * j][1]);
            float2 b0 = unpk(a1[2 * j + 1][0]), b1v = unpk(a1[2 * j + 1][1]);
            ulonglong2 o0, o1;
            o0.x = f2x2(a0.x, b0.x);  o0.y = f2x2(a0.y, b0.y);
            o1.x = f2x2(a1v.x, b1v.x); o1.y = f2x2(a1v.y, b1v.y);
            *(ulonglong2*)&V1[(ph0 + j) * VPU + c0]     = o0;
            *(ulonglong2*)&V1[(ph0 + j) * VPU + c0 + 2] = o1;
        }
    }
    {
        ull a2[8][2];
        mm_right8<0>(a2, B0, TU, r0, cg);
        store8(B2, a2, r0, c0);
        float4 pr = make_float4(0.f, 0.f, 0.f, 0.f);   // rs1 partials
        #pragma unroll
        for (int r = 0; r < 8; r++) {
            float sg = (r & 1) ? -1.f : 1.f;
            float2 u = unpk(a2[r][0]), w = unpk(a2[r][1]);
            pr.x += sg * u.x; pr.y += sg * u.y;
            pr.z += sg * w.x; pr.w += sg * w.y;
        }
        pr.x += __shfl_xor_sync(~0u, pr.x, 16);
        pr.y += __shfl_xor_sync(~0u, pr.y, 16);
        pr.z += __shfl_xor_sync(~0u, pr.z, 16);
        pr.w += __shfl_xor_sync(~0u, pr.w, 16);
        if (lane < 16) *(float4*)&Pr[wrp * 68 + c0] = pr;
    }
    __syncthreads();

    // ---- P2a: rs1/ts reduces + a3 = (Gx)G^T (vertical, row-pair) ----
    if (tid < 64) {
        float s = 0.f;
        #pragma unroll
        for (int w = 0; w < 4; w++) s += Pr[w * 68 + tid];
        rs1[tid] = s;
    } else if (tid < 96) {
        int l = tid - 64;
        float v = rs[2 * l] - rs[2 * l + 1];
        #pragma unroll
        for (int o = 16; o > 0; o >>= 1) v += __shfl_xor_sync(~0u, v, o);
        if (l == 0) tsp[0] = v;
    }
    ull a3[4][4];
    mm_rightV<0>(a3, V1, TD, ph0, cg);
    __syncthreads();

    // ---- P2b: corrections + squares:  B0<-oo^2(v)  B1<-eo^2(v)  B2<-oe^2(std) ----
    {
        float4 rv1 = *(const float4*)&rs1[c0];
        ull me[4];
        me[0] = f2x2( rv1.x * inv64, -rv1.x * inv64);
        me[1] = f2x2( rv1.y * inv64, -rv1.y * inv64);
        me[2] = f2x2( rv1.z * inv64, -rv1.z * inv64);
        me[3] = f2x2( rv1.w * inv64, -rv1.w * inv64);
        #pragma unroll
        for (int j = 0; j < 4; j++) {
            int ph = ph0 + j;
            int vrow = ph * VPU + c0;
            // --- oe^2 (from Gx vertical, col-alternating cs2 sign) -> B2 std ---
            ulonglong2 g0 = *(const ulonglong2*)&V1[vrow];
            ulonglong2 g1 = *(const ulonglong2*)&V1[vrow + 2];
            ull pc2  = f2x2( cs2[2 * ph] * inv64,  cs2[2 * ph + 1] * inv64);
            ull npc2 = f2x2(-cs2[2 * ph] * inv64, -cs2[2 * ph + 1] * inv64);
            ull q0 = addp(g0.x, pc2),  q1 = addp(g0.y, npc2);
            ull q2 = addp(g1.x, pc2),  q3 = addp(g1.y, npc2);
            q0 = mulp(q0, q0); q1 = mulp(q1, q1);
            q2 = mulp(q2, q2); q3 = mulp(q3, q3);
            // --- eo^2 (from xG^T std, row-alternating rs1 sign) -> B1 vertical ---
            float4 w0 = *(const float4*)&B2[(2 * ph) * PITCH + c0];
            float4 w1 = *(const float4*)&B2[(2 * ph + 1) * PITCH + c0];
            ull e0 = addp(f2x2(w0.x, w1.x), me[0]);
            ull e1 = addp(f2x2(w0.y, w1.y), me[1]);
            ull e2 = addp(f2x2(w0.z, w1.z), me[2]);
            ull e3 = addp(f2x2(w0.w, w1.w), me[3]);
            e0 = mulp(e0, e0); e1 = mulp(e1, e1);
            e2 = mulp(e2, e2); e3 = mulp(e3, e3);
            ulonglong2 ev0; ev0.x = e0; ev0.y = e1;
            ulonglong2 ev1; ev1.x = e2; ev1.y = e3;
            *(ulonglong2*)&V1[vrow]     = ev0;     // after g0/g1 reads
            *(ulonglong2*)&V1[vrow + 2] = ev1;
            // oe^2 std write (after w0/w1 reads)
            float2 u0 = unpk(q0), u1 = unpk(q1), u2 = unpk(q2), u3 = unpk(q3);
            *(float4*)&B2[(2 * ph) * PITCH + c0]     = make_float4(u0.x, u1.x, u2.x, u3.x);
            *(float4*)&B2[(2 * ph + 1) * PITCH + c0] = make_float4(u0.y, u1.y, u2.y, u3.y);
            // --- oo^2 from a3 (row-pair) -> B0 vertical ---
            ulonglong2 z0, z1;
            z0.x = mulp(a3[j][0], a3[j][0]); z0.y = mulp(a3[j][1], a3[j][1]);
            z1.x = mulp(a3[j][2], a3[j][2]); z1.y = mulp(a3[j][3], a3[j][3]);
            *(ulonglong2*)&V0[vrow]     = z0;
            *(ulonglong2*)&V0[vrow + 2] = z1;
        }
    }
    __syncthreads();

    // ---- P3: tmp = oe^2 + oo^2 G'^T  -> B2 std (own tile) ----
    {
        ull acc[4][4];
        mm_rightV<1>(acc, V0, TD, ph0, cg);
        #pragma unroll
        for (int j = 0; j < 4; j++) {
            int ph = ph0 + j;
            float4 w0 = *(const float4*)&B2[(2 * ph) * PITCH + c0];
            float4 w1 = *(const float4*)&B2[(2 * ph + 1) * PITCH + c0];
            float2 u0 = unpk(acc[j][0]), u1 = unpk(acc[j][1]),
                   u2 = unpk(acc[j][2]), u3 = unpk(acc[j][3]);
            *(float4*)&B2[(2 * ph) * PITCH + c0] =
                make_float4(w0.x + u0.x, w0.y + u1.x, w0.z + u2.x, w0.w + u3.x);
            *(float4*)&B2[(2 * ph + 1) * PITCH + c0] =
                make_float4(w1.x + u0.y, w1.y + u1.y, w1.z + u2.y, w1.w + u3.y);
        }
    }
    __syncthreads();

    // ---- P4: F = G'*tmp (left std) ; E = eo^2 G'^T (vertical) ; final combine ----
    {
        ull Fa[8][2];
        mm_left8<1>(Fa, B2, Dup, rg, c0);
        ull Ea[4][4];
        mm_rightV<1>(Ea, V1, TD, ph0, cg);
        const float ts = tsp[0];
        const float inv4096 = inv64 * inv64;
        float4 rv = *(const float4*)&rs[c0];
        #pragma unroll
        for (int r = 0; r < 8; r++) {
            int i = r0 + r;
            float sgni = (i & 1) ? -1.f : 1.f;
            float4 xv = *(const float4*)&xin[i * 64 + c0];
            float2 f0 = unpk(Fa[r][0]), f1 = unpk(Fa[r][1]);
            int j = r >> 1;
            float2 ea = unpk(Ea[j][0]), eb = unpk(Ea[j][1]);
            float2 ec = unpk(Ea[j][2]), ed = unpk(Ea[j][3]);
            float E0 = (r & 1) ? ea.y : ea.x;
            float E1 = (r & 1) ? eb.y : eb.x;
            float E2 = (r & 1) ? ec.y : ec.x;
            float E3 = (r & 1) ? ed.y : ed.x;
            float csv = cs[i] * inv64;
            float tci = sgni * ts * inv4096;
            float vx = xv.x + sgni * rv.x * inv64 + csv + tci;
            float vy = xv.y + sgni * rv.y * inv64 - csv - tci;
            float vz = xv.z + sgni * rv.z * inv64 + csv + tci;
            float vw = xv.w + sgni * rv.w * inv64 - csv - tci;
            float4 o;
            o.x = k0 + k1 * xv.x + k2q * (vx * vx + E0 + f0.x);
            o.y = k0 + k1 * xv.y + k2q * (vy * vy + E1 + f0.y);
            o.z = k0 + k1 * xv.z + k2q * (vz * vz + E2 + f1.x);
            o.w = k0 + k1 * xv.w + k2q * (vw * vw + E3 + f1.y);
            *(float4*)&outp[i * 64 + c0] = o;
        }
    }
}

// Host-side taps (double precision, exact integer angle reduction; 64-periodic).
static double host_g(int t) {
    const double PI_D = 3.14159265358979323846;
    long long m = 2LL * t + 1;
    int r1 = (int)(((63LL * m) % 256 + 256) % 256); if (r1 >= 128) r1 -= 256;
    int r2 = (int)((m % 256 + 256) % 256);          if (r2 >= 128) r2 -= 256;
    return (sin(PI_D * r1 / 128.0) / sin(PI_D * r2 / 128.0)) / 64.0;
}

extern "C" void kernel_launch(void* const* d_in, const int* in_sizes, int n_in,
                              void* d_out, int out_size) {
    const float* x    = (const float*)d_in[0];
    const float* coef = (const float*)d_in[1];
    float* out = (float*)d_out;

    static TapParam tab;
    static bool tab_init = false;
    if (!tab_init) {
        for (int m = 0; m < 36; m++)
            for (int rg = 0; rg < 8; rg++) {
                int s = 8 * rg + 2 * m - 64;
                float g0 = (float)host_g(s), g1 = (float)host_g(s + 1);
                tab.d[m * 8 + rg] = make_float4(g0, g0, g1, g1);
            }
        for (int m = 0; m < 34; m++)
            for (int c = 0; c < 16; c++) {
                int s = 4 * c + 2 * m - 64;
                float g0 = (float)host_g(s);
                float g1 = (float)host_g(s + 1);
                float g2 = (float)host_g(s + 2);
                tab.p[m * 16 + c]  = make_float4(g0, g1, g1, g2);
                tab.td[m * 16 + c] = make_float4(g0, g0, g1, g1);
            }
        tab_init = true;
    }

    // 3 buffers + Dup(288) + TU(544) + TD(544) x16B + Pr(272) + scratch(257)
    int smem_bytes = 3 * NB * (int)sizeof(float)
                   + (288 + 544 + 544) * 16
                   + (272 + 4 * 64 + 4) * (int)sizeof(float);   // 76356 B
    cudaFuncSetAttribute(uppolyact_kernel,
                         cudaFuncAttributeMaxDynamicSharedMemorySize, smem_bytes);

    int nimg = in_sizes[0] / 4096;   // 4096 images of 64x64
    uppolyact_kernel<<<nimg, 128, smem_bytes>>>(x, coef, out, tab);
}

// round 12
// speedup vs baseline: 1.1184x; 1.1184x over previous
#include <cuda_runtime.h>
#include <cmath>

#define PITCH 68
#define NB (64 * PITCH)   // 4352 floats per padded 64x64 buffer

typedef unsigned long long ull;

// Host-built tap tables, passed by value (~13.3 KB in kernel param space).
// d[m*8+rg]  = {g(s),g(s),g(s+1),g(s+1)},   s = 8*rg + 2*m - 64   (dup-quads, left)
// p[m*16+c]  = {g(s),g(s+1),g(s+1),g(s+2)}, s = 4*c  + 2*m - 64   (pair-quads, right)
struct TapParam { float4 d[288]; float4 p[544]; };

__device__ __forceinline__ ull f2x2(float lo, float hi) {
    ull r; asm("mov.b64 %0, {%1, %2};" : "=l"(r) : "f"(lo), "f"(hi)); return r;
}
__device__ __forceinline__ float2 unpk(ull v) {
    float2 r; asm("mov.b64 {%0, %1}, %2;" : "=f"(r.x), "=f"(r.y) : "l"(v)); return r;
}
__device__ __forceinline__ void ffma2(ull& d, ull a, ull b) {
    asm("fma.rn.f32x2 %0, %1, %2, %0;" : "+l"(d) : "l"(a), "l"(b));
}

// Left dup taps: t[w] = dup g(8rg - kb - 7 - SH + w), w in [0,15). 8 broadcast LDS.128.
template<int SH>
__device__ __forceinline__ void load_ldtaps(ull t[15], const ulonglong2* __restrict__ D,
                                            int kb, int rg) {
    const ulonglong2* dp = D + (28 - (kb >> 1)) * 8 + rg;
    ulonglong2 e[8];
    #pragma unroll
    for (int j = 0; j < 8; j++) e[j] = dp[j * 8];
    #pragma unroll
    for (int w = 0; w < 15; w++) {
        if (SH == 0) t[w] = (w & 1) ? e[(w + 1) >> 1].x : e[w >> 1].y;
        else         t[w] = (w & 1) ? e[w >> 1].y       : e[w >> 1].x;
    }
}

// Right pair taps: t[w] = pair(row u0+w), u0 = 57-SH-kb.
template<int SH>
__device__ __forceinline__ void load_rtaps(ull t[10], const ulonglong2* __restrict__ TU,
                                           int kb, int cg) {
    const ulonglong2* tp = TU + (28 - (kb >> 1)) * 16 + cg;
    ulonglong2 e[6];
    #pragma unroll
    for (int j = 0; j < (SH ? 5 : 6); j++) e[j] = tp[j * 16];
    #pragma unroll
    for (int w = 0; w < 10; w++) {
        if (SH) t[w] = (w & 1) ? e[w >> 1].y : e[w >> 1].x;
        else    t[w] = (w & 1) ? e[(w + 1) >> 1].x : e[w >> 1].y;
    }
}

// Left circulant, 8x4 tile, col-pair acc, MOV-free:
// acc[r][p] = {dst[8rg+r][c0+2p], dst[8rg+r][c0+2p+1]}, dst = sum_k g(i-k-SH) src[k][:]
template<int SH>
__device__ __forceinline__ void mm_left8(ull acc[8][2], const float* __restrict__ src,
                                         const ulonglong2* __restrict__ D,
                                         int rg, int c0) {
    #pragma unroll
    for (int r = 0; r < 8; r++) { acc[r][0] = 0ull; acc[r][1] = 0ull; }
    #pragma unroll 2
    for (int kb = 0; kb < 64; kb += 8) {
        ull t[15];
        load_ldtaps<SH>(t, D, kb, rg);
        #pragma unroll
        for (int q = 0; q < 8; q++) {
            ulonglong2 s = *(const ulonglong2*)&src[(kb + q) * PITCH + c0];
            #pragma unroll
            for (int r = 0; r < 8; r++) {
                ull a = t[r - q + 7];         // dup g((8rg+r)-(kb+q)-SH)
                ffma2(acc[r][0], a, s.x);
                ffma2(acc[r][1], a, s.y);
            }
        }
    }
}

// Right circulant^T, 8x4 tile, col-pair acc:
// acc[i][p] = {dst[r0+i][c0+2p], dst[r0+i][c0+2p+1]}, dst[i][m] = sum_k src[i][k] g(m-k-SH)
template<int SH>
__device__ __forceinline__ void mm_right8(ull acc[8][2], const float* __restrict__ src,
                                          const ulonglong2* __restrict__ TU,
                                          int r0, int cg) {
    #pragma unroll
    for (int r = 0; r < 8; r++) { acc[r][0] = 0ull; acc[r][1] = 0ull; }
    #pragma unroll 2
    for (int kb = 0; kb < 64; kb += 8) {
        ull t[10];
        load_rtaps<SH>(t, TU, kb, cg);
        #pragma unroll
        for (int i = 0; i < 8; i++) {
            float4 va = *(const float4*)&src[(r0 + i) * PITCH + kb];
            float4 vb = *(const float4*)&src[(r0 + i) * PITCH + kb + 4];
            float sv[8] = {va.x, va.y, va.z, va.w, vb.x, vb.y, vb.z, vb.w};
            #pragma unroll
            for (int q = 0; q < 8; q++) {
                ull sd = f2x2(sv[q], sv[q]);
                ffma2(acc[i][0], sd, t[7 - q]);   // pair(c0   - (kb+q) - SH)
                ffma2(acc[i][1], sd, t[9 - q]);   // pair(c0+2 - (kb+q) - SH)
            }
        }
    }
}

__device__ __forceinline__ void store8(float* __restrict__ dst, ull acc[8][2],
                                       int r0, int c0) {
    #pragma unroll
    for (int r = 0; r < 8; r++) {
        ulonglong2 o; o.x = acc[r][0]; o.y = acc[r][1];
        *(ulonglong2*)&dst[(r0 + r) * PITCH + c0] = o;
    }
}

__global__ void __launch_bounds__(128, 3)
uppolyact_kernel(const float* __restrict__ xg,
                 const float* __restrict__ coef,
                 float* __restrict__ outg,
                 const TapParam tab) {
    extern __shared__ float sm[];
    float* B0 = sm;            // x -> oo^2
    float* B1 = sm + NB;       // Gx -> oe^2 -> tmp
    float* B2 = sm + 2 * NB;   // xG^T -> eo^2
    ulonglong2* Dup = (ulonglong2*)(sm + 3 * NB);  // 288 entries
    ulonglong2* TU  = Dup + 288;                   // 544 entries
    float* Pr  = (float*)(TU + 544);   // 8 x 68
    float* Pc  = Pr + 544;             // 16 x 68
    float* rs  = Pc + 1088;            // 64
    float* cs  = rs + 64;              // 64
    float* rs1 = cs + 64;              // 64
    float* cs2 = rs1 + 64;             // 64
    float* tsp = cs2 + 64;             // 1

    const int tid = threadIdx.x;
    const int rg = tid >> 4, cg = tid & 15;
    const int r0 = rg << 3, c0 = cg << 2;
    const float* xin = xg + (size_t)blockIdx.x * 4096;
    float* outp = outg + (size_t)blockIdx.x * 4096;
    const float inv64 = 1.0f / 64.0f;

    const float k0 = __ldg(&coef[0]), k1 = __ldg(&coef[1]);
    const float k2q = 0.25f * __ldg(&coef[2]);

    // ---- P0: tables -> smem; load image; x rank-1 partials ----
    {
        const float4* dp = tab.d;  float4* dd = (float4*)Dup;
        #pragma unroll
        for (int i = tid; i < 288; i += 128) dd[i] = dp[i];
        const float4* pp = tab.p;  float4* pd = (float4*)TU;
        #pragma unroll
        for (int i = tid; i < 544; i += 128) pd[i] = pp[i];
    }
    {
        float4 xv[8];
        #pragma unroll
        for (int r = 0; r < 8; r++) {
            xv[r] = *(const float4*)&xin[(r0 + r) * 64 + c0];
            *(float4*)&B0[(r0 + r) * PITCH + c0] = xv[r];
        }
        float4 pr = make_float4(0.f, 0.f, 0.f, 0.f);   // alt-sum over 8 rows (r0 even)
        #pragma unroll
        for (int r = 0; r < 8; r++) {
            float sg = (r & 1) ? -1.f : 1.f;
            pr.x += sg * xv[r].x; pr.y += sg * xv[r].y;
            pr.z += sg * xv[r].z; pr.w += sg * xv[r].w;
        }
        *(float4*)&Pr[rg * 68 + c0] = pr;
        float pc[8];                                    // alt-sum over 4 cols (c0 even)
        #pragma unroll
        for (int r = 0; r < 8; r++)
            pc[r] = xv[r].x - xv[r].y + xv[r].z - xv[r].w;
        *(float4*)&Pc[cg * 68 + r0]     = make_float4(pc[0], pc[1], pc[2], pc[3]);
        *(float4*)&Pc[cg * 68 + r0 + 4] = make_float4(pc[4], pc[5], pc[6], pc[7]);
    }
    __syncthreads();

    // ---- P1: rs/cs reduce (tid<64) + a1 = Gx ; a2 = xG^T ----
    if (tid < 64) {
        float s = 0.f, t = 0.f;
        #pragma unroll
        for (int g = 0; g < 8; g++)  s += Pr[g * 68 + tid];
        #pragma unroll
        for (int g = 0; g < 16; g++) t += Pc[g * 68 + tid];
        rs[tid] = s; cs[tid] = t;
    }
    {
        ull a1[8][2];
        mm_left8<0>(a1, B0, Dup, rg, c0);
        store8(B1, a1, r0, c0);
        float pc[8];   // cs2 partials: alt col-sums of Gx per row
        #pragma unroll
        for (int r = 0; r < 8; r++) {
            float2 u = unpk(a1[r][0]), w = unpk(a1[r][1]);
            pc[r] = u.x - u.y + w.x - w.y;
        }
        *(float4*)&Pc[cg * 68 + r0]     = make_float4(pc[0], pc[1], pc[2], pc[3]);
        *(float4*)&Pc[cg * 68 + r0 + 4] = make_float4(pc[4], pc[5], pc[6], pc[7]);
    }
    {
        ull a2[8][2];
        mm_right8<0>(a2, B0, TU, r0, cg);
        store8(B2, a2, r0, c0);
        float4 pr = make_float4(0.f, 0.f, 0.f, 0.f);   // rs1 partials: alt row-sums of xG^T
        #pragma unroll
        for (int r = 0; r < 8; r++) {
            float sg = (r & 1) ? -1.f : 1.f;
            float2 u = unpk(a2[r][0]), w = unpk(a2[r][1]);
            pr.x += sg * u.x; pr.y += sg * u.y;
            pr.z += sg * w.x; pr.w += sg * w.y;
        }
        *(float4*)&Pr[rg * 68 + c0] = pr;
    }
    __syncthreads();

    // ---- P2a: rs1/cs2/ts reduces + a3 = (Gx)G^T ----
    if (tid < 64) {
        float s = 0.f, t = 0.f;
        #pragma unroll
        for (int g = 0; g < 8; g++)  s += Pr[g * 68 + tid];
        #pragma unroll
        for (int g = 0; g < 16; g++) t += Pc[g * 68 + tid];
        rs1[tid] = s; cs2[tid] = t;
    } else if (tid < 96) {
        int l = tid - 64;
        float v = rs[2 * l] - rs[2 * l + 1];
        #pragma unroll
        for (int o = 16; o > 0; o >>= 1) v += __shfl_xor_sync(~0u, v, o);
        if (l == 0) tsp[0] = v;
    }
    ull a3[8][2];
    mm_right8<0>(a3, B1, TU, r0, cg);
    __syncthreads();

    // ---- P2b: corrections + squares: B0<-oo^2 B1<-oe^2 B2<-eo^2 ----
    {
        float4 rv1 = *(const float4*)&rs1[c0];
        #pragma unroll
        for (int r = 0; r < 8; r++) {
            int i = r0 + r;
            float sgni = (i & 1) ? -1.f : 1.f;
            float cs2v = cs2[i] * inv64;
            int base = i * PITCH + c0;
            float4 v1 = *(float4*)&B1[base];   // Gx   -> oe
            float4 v2 = *(float4*)&B2[base];   // xG^T -> eo
            float2 o0 = unpk(a3[r][0]), o1 = unpk(a3[r][1]);
            float4 eo, oe, oo;
            eo.x = v2.x + sgni * rv1.x * inv64;
            eo.y = v2.y + sgni * rv1.y * inv64;
            eo.z = v2.z + sgni * rv1.z * inv64;
            eo.w = v2.w + sgni * rv1.w * inv64;
            oe.x = v1.x + cs2v;  oe.y = v1.y - cs2v;
            oe.z = v1.z + cs2v;  oe.w = v1.w - cs2v;
            oo.x = o0.x; oo.y = o0.y; oo.z = o1.x; oo.w = o1.y;
            eo.x *= eo.x; eo.y *= eo.y; eo.z *= eo.z; eo.w *= eo.w;
            oe.x *= oe.x; oe.y *= oe.y; oe.z *= oe.z; oe.w *= oe.w;
            oo.x *= oo.x; oo.y *= oo.y; oo.z *= oo.z; oo.w *= oo.w;
            *(float4*)&B2[base] = eo;
            *(float4*)&B1[base] = oe;
            *(float4*)&B0[base] = oo;
        }
    }
    __syncthreads();

    // ---- P3: tmp: B1 = oe^2 + oo^2 G'^T  (own-tile in-place) ----
    {
        ull acc[8][2];
        mm_right8<1>(acc, B0, TU, r0, cg);
        #pragma unroll
        for (int r = 0; r < 8; r++) {
            int base = (r0 + r) * PITCH + c0;
            float4 d = *(float4*)&B1[base];
            float2 a0 = unpk(acc[r][0]), a1 = unpk(acc[r][1]);
            d.x += a0.x;  d.y += a0.y;  d.z += a1.x;  d.w += a1.y;
            *(float4*)&B1[base] = d;
        }
    }
    __syncthreads();

    // ---- P4+P5: F = G'*tmp (left), E = eo^2 G'^T (right), final combine ----
    {
        ull Fa[8][2];
        mm_left8<1>(Fa, B1, Dup, rg, c0);
        ull Ea[8][2];
        mm_right8<1>(Ea, B2, TU, r0, cg);
        const float ts = tsp[0];
        const float inv4096 = inv64 * inv64;
        float4 rv = *(const float4*)&rs[c0];
        #pragma unroll
        for (int r = 0; r < 8; r++) {
            int i = r0 + r;
            float sgni = (i & 1) ? -1.f : 1.f;
            float4 xv = *(const float4*)&xin[i * 64 + c0];
            float2 f0 = unpk(Fa[r][0]), f1 = unpk(Fa[r][1]);
            float2 e0 = unpk(Ea[r][0]), e1 = unpk(Ea[r][1]);
            float csv = cs[i] * inv64;
            float tci = sgni * ts * inv4096;
            float vx = xv.x + sgni * rv.x * inv64 + csv + tci;
            float vy = xv.y + sgni * rv.y * inv64 - csv - tci;
            float vz = xv.z + sgni * rv.z * inv64 + csv + tci;
            float vw = xv.w + sgni * rv.w * inv64 - csv - tci;
            float4 o;
            o.x = k0 + k1 * xv.x + k2q * (vx * vx + e0.x + f0.x);
            o.y = k0 + k1 * xv.y + k2q * (vy * vy + e0.y + f0.y);
            o.z = k0 + k1 * xv.z + k2q * (vz * vz + e1.x + f1.x);
            o.w = k0 + k1 * xv.w + k2q * (vw * vw + e1.y + f1.y);
            *(float4*)&outp[i * 64 + c0] = o;
        }
    }
}

// Host-side taps (double precision, exact integer angle reduction; 64-periodic).
static double host_g(int t) {
    const double PI_D = 3.14159265358979323846;
    long long m = 2LL * t + 1;
    int r1 = (int)(((63LL * m) % 256 + 256) % 256); if (r1 >= 128) r1 -= 256;
    int r2 = (int)((m % 256 + 256) % 256);          if (r2 >= 128) r2 -= 256;
    return (sin(PI_D * r1 / 128.0) / sin(PI_D * r2 / 128.0)) / 64.0;
}

extern "C" void kernel_launch(void* const* d_in, const int* in_sizes, int n_in,
                              void* d_out, int out_size) {
    const float* x    = (const float*)d_in[0];
    const float* coef = (const float*)d_in[1];
    float* out = (float*)d_out;

    static TapParam tab;
    static bool tab_init = false;
    if (!tab_init) {
        for (int m = 0; m < 36; m++)
            for (int rg = 0; rg < 8; rg++) {
                int s = 8 * rg + 2 * m - 64;
                float g0 = (float)host_g(s), g1 = (float)host_g(s + 1);
                tab.d[m * 8 + rg] = make_float4(g0, g0, g1, g1);
            }
        for (int m = 0; m < 34; m++)
            for (int c = 0; c < 16; c++) {
                int s = 4 * c + 2 * m - 64;
                float g0 = (float)host_g(s);
                float g1 = (float)host_g(s + 1);
                float g2 = (float)host_g(s + 2);
                tab.p[m * 16 + c] = make_float4(g0, g1, g1, g2);
            }
        tab_init = true;
    }

    // 3 buffers + Dup(288x16B) + TU(544x16B) + Pr/Pc + scratch
    int smem_bytes = 3 * NB * (int)sizeof(float)
                   + (288 + 544) * 16
                   + (544 + 1088 + 4 * 64 + 4) * (int)sizeof(float);   // ~73.1 KB
    cudaFuncSetAttribute(uppolyact_kernel,
                         cudaFuncAttributeMaxDynamicSharedMemorySize, smem_bytes);

    int nimg = in_sizes[0] / 4096;   // 4096 images of 64x64
    uppolyact_kernel<<<nimg, 128, smem_bytes>>>(x, coef, out, tab);
}